// round 13
// baseline (speedup 1.0000x reference)
#include <cuda_runtime.h>
#include <cuda_bf16.h>
#include <cuda_fp16.h>
#include <math.h>
#include <stdint.h>

// Problem constants
#define B    8
#define S    2048
#define CLIP 512
#define H    512
#define BN   256
#define NC   10
#define LN_EPS 1e-5f
#define M_TOT (B * S)   // 16384

#if defined(__CUDA_ARCH_FEAT_SM103_ALL) || defined(__CUDA_ARCH_FEAT_SM100_ALL) || defined(__CUDA_ARCH_FEAT_SM101_ALL)
#define HAS_TCGEN05 1
#else
#define HAS_TCGEN05 0
#endif

// ---------------------------------------------------------------------------
// Scratch
// ---------------------------------------------------------------------------
__device__ float g_tmp[M_TOT * H];              // enc pre-LN
__device__ __align__(256) __half g_scores_h[(size_t)B * S * S];   // fp16 scores
__device__ float g_bn[M_TOT * BN];              // bottleneck pre-LN
__device__ float g_pp[B * 8 * BN];              // pool partials

__device__ __align__(256) __nv_bfloat16 g_lf_h[M_TOT * CLIP], g_lf_l[M_TOT * CLIP];
__device__ __align__(256) __nv_bfloat16 g_h_h[M_TOT * H],  g_h_l[M_TOT * H];
__device__ __align__(256) __nv_bfloat16 g_q_h[M_TOT * H],  g_q_l[M_TOT * H];
__device__ __align__(256) __nv_bfloat16 g_k_h[M_TOT * H],  g_k_l[M_TOT * H];
__device__ __align__(256) __nv_bfloat16 g_v_h[M_TOT * H],  g_v_l[M_TOT * H];
__device__ __align__(256) __nv_bfloat16 g_vt_h[B * H * S], g_vt_l[B * H * S];
__device__ __align__(256) __nv_bfloat16 g_at_h[(size_t)B * S * S];
__device__ __align__(256) __nv_bfloat16 g_hg_h[M_TOT * H], g_hg_l[M_TOT * H];
__device__ __align__(256) __nv_bfloat16 g_we_h[H * CLIP],  g_we_l[H * CLIP];
__device__ __align__(256) __nv_bfloat16 g_wq_h[H * H],     g_wq_l[H * H];
__device__ __align__(256) __nv_bfloat16 g_wk_h[H * H],     g_wk_l[H * H];
__device__ __align__(256) __nv_bfloat16 g_wv_h[H * H],     g_wv_l[H * H];
__device__ __align__(256) __nv_bfloat16 g_wb_h[BN * H],    g_wb_l[BN * H];

#define TILE_M2 256     // M per CTA (2 TMEM accumulators of 128 rows)
#define TILE_N 256
#define KC 32           // K per chunk (SW64, 64B rows)
#define NSTG 3          // pipeline stages
#define GEMM_SMEM_BYTES (NSTG * 65536 + 1024)

#if HAS_TCGEN05
// ---------------------------------------------------------------------------
// PTX helpers (tcgen05 / mbarrier / cp.async, sm_103a)
// ---------------------------------------------------------------------------
__device__ __forceinline__ uint32_t smem_u32(const void* p) {
    return (uint32_t)__cvta_generic_to_shared(p);
}
__device__ __forceinline__ bool elect_one() {
    uint32_t pred;
    asm volatile("{\n\t.reg .pred p;\n\telect.sync _|p, 0xFFFFFFFF;\n\tselp.b32 %0, 1, 0, p;\n\t}"
                 : "=r"(pred));
    return pred != 0;
}
__device__ __forceinline__ void mbar_init(uint32_t a, uint32_t cnt) {
    asm volatile("mbarrier.init.shared.b64 [%0], %1;" :: "r"(a), "r"(cnt) : "memory");
}
__device__ __forceinline__ void mbar_inval(uint32_t a) {
    asm volatile("mbarrier.inval.shared.b64 [%0];" :: "r"(a) : "memory");
}
__device__ __forceinline__ void mbar_wait(uint32_t a, uint32_t parity) {
    asm volatile(
        "{\n\t.reg .pred P;\n"
        "W_%=:\n\t"
        "mbarrier.try_wait.parity.acquire.cta.shared::cta.b64 P, [%0], %1, 0x989680;\n\t"
        "@P bra.uni D_%=;\n\t"
        "bra.uni W_%=;\n"
        "D_%=:\n\t}"
        :: "r"(a), "r"(parity) : "memory");
}
__device__ __forceinline__ void tc_alloc(uint32_t smem_ptr_addr, uint32_t ncols) {
    asm volatile("tcgen05.alloc.cta_group::1.sync.aligned.shared::cta.b32 [%0], %1;"
                 :: "r"(smem_ptr_addr), "r"(ncols) : "memory");
}
__device__ __forceinline__ void tc_dealloc(uint32_t tmem, uint32_t ncols) {
    asm volatile("tcgen05.dealloc.cta_group::1.sync.aligned.b32 %0, %1;" :: "r"(tmem), "r"(ncols));
}
__device__ __forceinline__ void tc_relinquish() {
    asm volatile("tcgen05.relinquish_alloc_permit.cta_group::1.sync.aligned;");
}
__device__ __forceinline__ void tc_commit(uint32_t mbar) {
    asm volatile("tcgen05.commit.cta_group::1.mbarrier::arrive::one.shared::cluster.b64 [%0];"
                 :: "r"(mbar) : "memory");
}
__device__ __forceinline__ void tc_fence_after() {
    asm volatile("tcgen05.fence::after_thread_sync;" ::: "memory");
}
__device__ __forceinline__ void tc_wait_ld() {
    asm volatile("tcgen05.wait::ld.sync.aligned;" ::: "memory");
}
__device__ __forceinline__ void mma_ss(uint32_t d, uint64_t a, uint64_t b, uint32_t idesc, uint32_t en) {
    asm volatile(
        "{\n\t"
        ".reg .pred p;\n\t"
        "setp.ne.u32 p, %5, 0;\n\t"
        "tcgen05.mma.cta_group::1.kind::f16 [%0], %1, %2, %3, {%4, %4, %4, %4}, p;\n\t"
        "}"
        :: "r"(d), "l"(a), "l"(b), "r"(idesc), "r"(0u), "r"(en) : "memory");
}
__device__ __forceinline__ void ldtm_x32(uint32_t* r, uint32_t addr) {
    asm volatile(
        "tcgen05.ld.sync.aligned.32x32b.x32.b32 "
        "{%0, %1, %2, %3, %4, %5, %6, %7, "
        " %8, %9, %10, %11, %12, %13, %14, %15, "
        " %16, %17, %18, %19, %20, %21, %22, %23, "
        " %24, %25, %26, %27, %28, %29, %30, %31}, [%32];"
        : "=r"(r[0]),  "=r"(r[1]),  "=r"(r[2]),  "=r"(r[3]),
          "=r"(r[4]),  "=r"(r[5]),  "=r"(r[6]),  "=r"(r[7]),
          "=r"(r[8]),  "=r"(r[9]),  "=r"(r[10]), "=r"(r[11]),
          "=r"(r[12]), "=r"(r[13]), "=r"(r[14]), "=r"(r[15]),
          "=r"(r[16]), "=r"(r[17]), "=r"(r[18]), "=r"(r[19]),
          "=r"(r[20]), "=r"(r[21]), "=r"(r[22]), "=r"(r[23]),
          "=r"(r[24]), "=r"(r[25]), "=r"(r[26]), "=r"(r[27]),
          "=r"(r[28]), "=r"(r[29]), "=r"(r[30]), "=r"(r[31])
        : "r"(addr));
}
// SW64: layout=4, version=1, SBO=32 (512B = 8 rows x 64B), LBO=1
__device__ __forceinline__ uint64_t make_desc64(uint32_t addr) {
    const uint64_t base = (4ull << 61) | (1ull << 46) | (32ull << 32) | (1ull << 16);
    return base | (uint64_t)((addr >> 4) & 0x3FFF);
}
__device__ __forceinline__ uint32_t swz64(uint32_t o) { return o ^ ((o >> 3) & 0x30); }
__device__ __forceinline__ void cp16(uint32_t dst, const void* src) {
    asm volatile("cp.async.cg.shared.global [%0], [%1], 16;" :: "r"(dst), "l"(src) : "memory");
}
__device__ __forceinline__ void cp_commit() { asm volatile("cp.async.commit_group;" ::: "memory"); }
__device__ __forceinline__ void cp_wait0()  { asm volatile("cp.async.wait_group 0;" ::: "memory"); }
__device__ __forceinline__ void cp_wait1()  { asm volatile("cp.async.wait_group 1;" ::: "memory"); }
#endif  // HAS_TCGEN05

// ---------------------------------------------------------------------------
// GEMM body: C = alpha * A @ B^T (+bias), split-bf16, tcgen05.
// M=256 per CTA (2 TMEM accumulators); B staged once per chunk, reused by
// both 128-row A halves. KC=32 (SW64), 3-stage cp.async pipeline.
// RACE FIX: the LAST chunk's MMA must wait_group 0 (its own staging group is
// the newest in flight; wait_group 1 would let it remain incomplete).
// ATERMS=2: A=Ah+Al; ATERMS=1: A=Ah. OMODE 0 fp32 / 1 bf16 hi-lo / 2 fp16.
// ---------------------------------------------------------------------------
template<bool BIAS, int OMODE, int ATERMS>
__device__ __forceinline__ void gemm_body(
    const __nv_bfloat16* __restrict__ Ah, const __nv_bfloat16* __restrict__ Al,
    const __nv_bfloat16* __restrict__ Bh, const __nv_bfloat16* __restrict__ Bl,
    const float* __restrict__ bias, float* __restrict__ C,
    __nv_bfloat16* __restrict__ CH, __nv_bfloat16* __restrict__ CL,
    int K, int ldC, float alpha, int mBase, int nBase, size_t cOff, char* dynsmem)
{
#if HAS_TCGEN05
    __shared__ uint32_t s_tmemptr[1];
    __shared__ __align__(8) uint64_t s_mbar[NSTG];

    constexpr uint32_t A_HALF = 8192;                    // 128 rows x 64B per term
    constexpr uint32_t A_BYTES = 2 * ATERMS * A_HALF;    // both halves
    constexpr uint32_t B_OFF = A_BYTES;
    constexpr uint32_t STAGE_SZ = A_BYTES + 32768;       // + Bh,Bl

    const int tid = threadIdx.x;
    uint32_t sraw = smem_u32(dynsmem);
    uint32_t sA = (sraw + 1023u) & ~1023u;

    uint32_t mb[NSTG];
    #pragma unroll
    for (int i = 0; i < NSTG; i++) mb[i] = smem_u32(&s_mbar[i]);
    const uint32_t tptr = smem_u32(s_tmemptr);

    if (tid == 0) {
        #pragma unroll
        for (int i = 0; i < NSTG; i++) mbar_init(mb[i], 1);
    }
    if (tid < 32) { tc_alloc(tptr, 512); tc_relinquish(); }
    __syncthreads();
    const uint32_t tmem = s_tmemptr[0];

    const uint32_t IDESC =
        (1u << 4) | (1u << 7) | (1u << 10) | ((TILE_N / 8) << 17) | ((128 / 16) << 24);

    const int nch = K / KC;
    int phase[NSTG] = {0, 0, 0};

    auto stage = [&](int ch, uint32_t stOff) {
        const int k0 = ch * KC;
        #pragma unroll
        for (int it = 0; it < 4; it++) {
            int idx = tid + it * 256;            // 0..1023: A (2 halves x 128 rows)
            int hf = idx >> 9;
            int row = (idx >> 2) & 127;
            int c = idx & 3;
            size_t go = (size_t)(mBase + hf * 128 + row) * K + k0 + c * 8;
            uint32_t so = swz64((uint32_t)(row * 64 + c * 16));
            uint32_t aoff = stOff + (uint32_t)hf * (ATERMS * A_HALF);
            cp16(sA + aoff + so, Ah + go);
            if (ATERMS == 2) cp16(sA + aoff + A_HALF + so, Al + go);
        }
        #pragma unroll
        for (int it = 0; it < 4; it++) {
            int idx = tid + it * 256;            // 0..1023: B (256 rows)
            int row = idx >> 2;
            int c = idx & 3;
            size_t go = (size_t)(nBase + row) * K + k0 + c * 8;
            uint32_t so = swz64((uint32_t)(row * 64 + c * 16));
            cp16(sA + stOff + B_OFF + so, Bh + go);
            cp16(sA + stOff + B_OFF + 16384 + so, Bl + go);
        }
        cp_commit();
    };

    // Prologue: stage chunks 0 and 1 (nch >= 3 for all our GEMMs)
    stage(0, 0);
    stage(1, STAGE_SZ);

    for (int ch = 0; ch < nch; ch++) {
        const int bi = ch % NSTG;
        const uint32_t stOff = (uint32_t)bi * STAGE_SZ;

        // RACE FIX: for the final chunk, its own staging group is the newest
        // in flight -> must drain ALL groups. Otherwise keep 1 in flight.
        if (ch == nch - 1) cp_wait0(); else cp_wait1();
        __syncthreads();

        if (tid < 32) {
            asm volatile("fence.proxy.async.shared::cta;" ::: "memory");
            if (elect_one()) {
                uint64_t dBh = make_desc64(sA + stOff + B_OFF);
                uint64_t dBl = make_desc64(sA + stOff + B_OFF + 16384);
                #pragma unroll
                for (int acc = 0; acc < 2; acc++) {
                    uint64_t dAh = make_desc64(sA + stOff + (uint32_t)acc * (ATERMS * A_HALF));
                    uint64_t dAl = dAh + (A_HALF >> 4);
                    uint32_t dst = tmem + acc * 256;
                    #pragma unroll
                    for (int kk = 0; kk < 2; kk++) {
                        uint64_t o = (uint64_t)(kk * 2);
                        uint32_t en0 = (ch == 0 && kk == 0) ? 0u : 1u;
                        mma_ss(dst, dAh + o, dBh + o, IDESC, en0);
                        mma_ss(dst, dAh + o, dBl + o, IDESC, 1u);
                        if (ATERMS == 2) mma_ss(dst, dAl + o, dBh + o, IDESC, 1u);
                    }
                }
                tc_commit(mb[bi]);
            }
        }

        // Prefetch chunk ch+2 into buffer (ch+2)%NSTG; wait its previous MMA (ch-1).
        if (ch + 2 < nch) {
            const int ob = (ch + 2) % NSTG;
            if (ch >= 1) { mbar_wait(mb[ob], (uint32_t)(phase[ob] & 1)); phase[ob]++; }
            stage(ch + 2, (uint32_t)ob * STAGE_SZ);
        }
    }

    // Drain: each used buffer has one outstanding MMA commit.
    #pragma unroll
    for (int b2 = 0; b2 < NSTG; b2++)
        mbar_wait(mb[b2], (uint32_t)(phase[b2] & 1));
    tc_fence_after();

    // Epilogue: 8 warps x 2 accumulators; warp w -> subpartition w&3, col half w>>2.
    {
        int w = tid >> 5, lane = tid & 31;
        int sub = w & 3, half = w >> 2;
        #pragma unroll 1
        for (int acc = 0; acc < 2; acc++) {
            size_t m = (size_t)mBase + acc * 128 + sub * 32 + lane;
            #pragma unroll 1
            for (int c = 0; c < 4; c++) {
                int cg = half * 4 + c;
                uint32_t r[32];
                ldtm_x32(r, tmem + acc * 256 + cg * 32);
                tc_wait_ld();
                int colBase = nBase + cg * 32;
                if (OMODE == 0) {
                    float* dst = C + cOff + m * (size_t)ldC + colBase;
                    #pragma unroll
                    for (int j = 0; j < 32; j += 4) {
                        float4 o;
                        o.x = __uint_as_float(r[j + 0]) * alpha;
                        o.y = __uint_as_float(r[j + 1]) * alpha;
                        o.z = __uint_as_float(r[j + 2]) * alpha;
                        o.w = __uint_as_float(r[j + 3]) * alpha;
                        if (BIAS) {
                            const float* bp = bias + colBase + j;
                            o.x += bp[0]; o.y += bp[1]; o.z += bp[2]; o.w += bp[3];
                        }
                        *(float4*)(dst + j) = o;
                    }
                } else if (OMODE == 1) {
                    __nv_bfloat16* dh = CH + cOff + m * (size_t)ldC + colBase;
                    __nv_bfloat16* dl = CL + cOff + m * (size_t)ldC + colBase;
                    #pragma unroll
                    for (int j = 0; j < 32; j += 4) {
                        float v4[4];
                        #pragma unroll
                        for (int u = 0; u < 4; u++) {
                            float x = __uint_as_float(r[j + u]) * alpha;
                            if (BIAS) x += bias[colBase + j + u];
                            v4[u] = x;
                        }
                        ushort4 hp, lp;
                        __nv_bfloat16 hv0 = __float2bfloat16(v4[0]);
                        __nv_bfloat16 hv1 = __float2bfloat16(v4[1]);
                        __nv_bfloat16 hv2 = __float2bfloat16(v4[2]);
                        __nv_bfloat16 hv3 = __float2bfloat16(v4[3]);
                        __nv_bfloat16 lv0 = __float2bfloat16(v4[0] - __bfloat162float(hv0));
                        __nv_bfloat16 lv1 = __float2bfloat16(v4[1] - __bfloat162float(hv1));
                        __nv_bfloat16 lv2 = __float2bfloat16(v4[2] - __bfloat162float(hv2));
                        __nv_bfloat16 lv3 = __float2bfloat16(v4[3] - __bfloat162float(hv3));
                        hp.x = *(unsigned short*)&hv0; hp.y = *(unsigned short*)&hv1;
                        hp.z = *(unsigned short*)&hv2; hp.w = *(unsigned short*)&hv3;
                        lp.x = *(unsigned short*)&lv0; lp.y = *(unsigned short*)&lv1;
                        lp.z = *(unsigned short*)&lv2; lp.w = *(unsigned short*)&lv3;
                        *(ushort4*)(dh + j) = hp;
                        *(ushort4*)(dl + j) = lp;
                    }
                } else {
                    __half* dst = reinterpret_cast<__half*>(CH) + cOff + m * (size_t)ldC + colBase;
                    #pragma unroll
                    for (int j = 0; j < 32; j += 8) {
                        __half2 h2[4];
                        #pragma unroll
                        for (int u = 0; u < 4; u++) {
                            float x0 = __uint_as_float(r[j + u * 2 + 0]) * alpha;
                            float x1 = __uint_as_float(r[j + u * 2 + 1]) * alpha;
                            h2[u] = __floats2half2_rn(x0, x1);
                        }
                        uint4 o;
                        o.x = *(uint32_t*)&h2[0]; o.y = *(uint32_t*)&h2[1];
                        o.z = *(uint32_t*)&h2[2]; o.w = *(uint32_t*)&h2[3];
                        *(uint4*)(dst + j) = o;
                    }
                }
            }
        }
    }
    __syncthreads();
    if (tid == 0) {
        #pragma unroll
        for (int i = 0; i < NSTG; i++) mbar_inval(mb[i]);
    }
    __syncthreads();
    if (tid < 32) tc_dealloc(tmem, 512);
#else
    // Fallback for non-sm_103a passes (correctness insurance only).
    const int tid = threadIdx.x;
    for (int idx = tid; idx < TILE_M2 * TILE_N; idx += 256) {
        int mi = mBase + idx / TILE_N;
        int ni = nBase + idx % TILE_N;
        float acc = 0.f;
        for (int kk = 0; kk < K; kk++) {
            float a = __bfloat162float(Ah[(size_t)mi * K + kk]);
            if (ATERMS == 2) a += __bfloat162float(Al[(size_t)mi * K + kk]);
            float b = __bfloat162float(Bh[(size_t)ni * K + kk]) + __bfloat162float(Bl[(size_t)ni * K + kk]);
            acc = fmaf(a, b, acc);
        }
        acc *= alpha;
        if (BIAS) acc += bias[ni];
        size_t off = cOff + (size_t)mi * ldC + ni;
        if (OMODE == 0) {
            C[off] = acc;
        } else if (OMODE == 1) {
            __nv_bfloat16 hv = __float2bfloat16(acc);
            CH[off] = hv;
            CL[off] = __float2bfloat16(acc - __bfloat162float(hv));
        } else {
            reinterpret_cast<__half*>(CH)[off] = __float2half(acc);
        }
    }
#endif
}

template<bool BIAS, int OMODE, int ATERMS>
__global__ __launch_bounds__(256)
void gemm_tc_kernel(const __nv_bfloat16* __restrict__ Ahi, const __nv_bfloat16* __restrict__ Alo,
                    const __nv_bfloat16* __restrict__ Bhi, const __nv_bfloat16* __restrict__ Blo,
                    const float* __restrict__ bias, float* __restrict__ C,
                    __nv_bfloat16* __restrict__ CH, __nv_bfloat16* __restrict__ CL,
                    int K, int ldC, float alpha,
                    size_t strA, size_t strB, size_t strC)
{
    extern __shared__ char dynsmem[];
    gemm_body<BIAS, OMODE, ATERMS>(
        Ahi + (size_t)blockIdx.z * strA, Alo + (size_t)blockIdx.z * strA,
        Bhi + (size_t)blockIdx.z * strB, Blo + (size_t)blockIdx.z * strB,
        bias, C, CH, CL, K, ldC, alpha,
        blockIdx.y * TILE_M2, blockIdx.x * TILE_N,
        (size_t)blockIdx.z * strC, dynsmem);
}

// Merged Q/K/V projection: blockIdx.z selects weight/bias/output set.
struct QKVArgs {
    const __nv_bfloat16* bh[3];
    const __nv_bfloat16* bl[3];
    const float* bias[3];
    __nv_bfloat16* ch[3];
    __nv_bfloat16* cl[3];
};

__global__ __launch_bounds__(256)
void qkv_kernel(const __nv_bfloat16* __restrict__ Ah, const __nv_bfloat16* __restrict__ Al,
                QKVArgs a)
{
    extern __shared__ char dynsmem[];
    int z = blockIdx.z;
    gemm_body<true, 1, 2>(Ah, Al, a.bh[z], a.bl[z], a.bias[z],
                          nullptr, a.ch[z], a.cl[z],
                          H, H, 1.f, blockIdx.y * TILE_M2, blockIdx.x * TILE_N, 0, dynsmem);
}

// No-op kernel: shifts launch indices so ncu (-s 5 -c 1) samples the encoder GEMM.
__global__ void noop_kernel() {}

// ---------------------------------------------------------------------------
// fp32 -> bf16 hi/lo split
// ---------------------------------------------------------------------------
__global__ void split_kernel(const float* __restrict__ in, __nv_bfloat16* __restrict__ hi,
                             __nv_bfloat16* __restrict__ lo, size_t n4)
{
    size_t i = (size_t)blockIdx.x * blockDim.x + threadIdx.x;
    if (i >= n4) return;
    float4 v = ((const float4*)in)[i];
    __nv_bfloat16 h0 = __float2bfloat16(v.x), h1 = __float2bfloat16(v.y);
    __nv_bfloat16 h2 = __float2bfloat16(v.z), h3 = __float2bfloat16(v.w);
    __nv_bfloat16 l0 = __float2bfloat16(v.x - __bfloat162float(h0));
    __nv_bfloat16 l1 = __float2bfloat16(v.y - __bfloat162float(h1));
    __nv_bfloat16 l2 = __float2bfloat16(v.z - __bfloat162float(h2));
    __nv_bfloat16 l3 = __float2bfloat16(v.w - __bfloat162float(h3));
    ushort4 hp, lp;
    hp.x = *(unsigned short*)&h0; hp.y = *(unsigned short*)&h1;
    hp.z = *(unsigned short*)&h2; hp.w = *(unsigned short*)&h3;
    lp.x = *(unsigned short*)&l0; lp.y = *(unsigned short*)&l1;
    lp.z = *(unsigned short*)&l2; lp.w = *(unsigned short*)&l3;
    ((ushort4*)hi)[i] = hp;
    ((ushort4*)lo)[i] = lp;
}

// ---------------------------------------------------------------------------
// bf16 pair transpose: [S,H] -> [H,S], z = b*2 + (hi/lo)
// ---------------------------------------------------------------------------
__global__ void transpose_bf16_kernel(const __nv_bfloat16* __restrict__ inH,
                                      const __nv_bfloat16* __restrict__ inL,
                                      __nv_bfloat16* __restrict__ outH,
                                      __nv_bfloat16* __restrict__ outL,
                                      int R, int C, size_t strIn, size_t strOut)
{
    __shared__ uint16_t t[32][33];
    int zz = blockIdx.z;
    int b = zz >> 1, which = zz & 1;
    const uint16_t* in = (const uint16_t*)(which ? inL : inH) + (size_t)b * strIn;
    uint16_t* out = (uint16_t*)(which ? outL : outH) + (size_t)b * strOut;
    int r0 = blockIdx.y * 32, c0 = blockIdx.x * 32;
    #pragma unroll
    for (int i = threadIdx.y; i < 32; i += 8)
        t[i][threadIdx.x] = in[(size_t)(r0 + i) * C + c0 + threadIdx.x];
    __syncthreads();
    #pragma unroll
    for (int i = threadIdx.y; i < 32; i += 8)
        out[(size_t)(c0 + i) * R + r0 + threadIdx.x] = t[threadIdx.x][i];
}

// ---------------------------------------------------------------------------
// Combined weight transpose+split: all 5 weights, z = which.
// ---------------------------------------------------------------------------
struct WTArgs {
    const float* in[5];
    __nv_bfloat16* hi[5];
    __nv_bfloat16* lo[5];
    int R[5];
    int C[5];
};

__global__ void weights_transpose_kernel(WTArgs a)
{
    __shared__ float t[32][33];
    int z = blockIdx.z;
    int R = a.R[z], C = a.C[z];
    int r0 = blockIdx.y * 32, c0 = blockIdx.x * 32;
    if (r0 >= R || c0 >= C) return;
    const float* inb = a.in[z];
    #pragma unroll
    for (int i = threadIdx.y; i < 32; i += 8)
        t[i][threadIdx.x] = inb[(size_t)(r0 + i) * C + c0 + threadIdx.x];
    __syncthreads();
    #pragma unroll
    for (int i = threadIdx.y; i < 32; i += 8) {
        float x = t[threadIdx.x][i];
        __nv_bfloat16 hv = __float2bfloat16(x);
        __nv_bfloat16 lv = __float2bfloat16(x - __bfloat162float(hv));
        size_t o = (size_t)(c0 + i) * R + r0 + threadIdx.x;
        a.hi[z][o] = hv; a.lo[z][o] = lv;
    }
}

// ---------------------------------------------------------------------------
// Reductions
// ---------------------------------------------------------------------------
__device__ __forceinline__ float warpReduceSum(float v) {
    #pragma unroll
    for (int o = 16; o > 0; o >>= 1) v += __shfl_xor_sync(0xffffffffu, v, o);
    return v;
}
__device__ __forceinline__ float warpReduceMax(float v) {
    #pragma unroll
    for (int o = 16; o > 0; o >>= 1) v = fmaxf(v, __shfl_xor_sync(0xffffffffu, v, o));
    return v;
}
__device__ float blockReduceSum(float v) {
    __shared__ float sh[33];
    int lane = threadIdx.x & 31, wid = threadIdx.x >> 5;
    int nw = (blockDim.x + 31) >> 5;
    v = warpReduceSum(v);
    __syncthreads();
    if (lane == 0) sh[wid] = v;
    __syncthreads();
    if (wid == 0) {
        float x = (lane < nw) ? sh[lane] : 0.f;
        x = warpReduceSum(x);
        if (lane == 0) sh[32] = x;
    }
    __syncthreads();
    return sh[32];
}
__device__ float blockReduceMax(float v) {
    __shared__ float sh[33];
    int lane = threadIdx.x & 31, wid = threadIdx.x >> 5;
    int nw = (blockDim.x + 31) >> 5;
    v = warpReduceMax(v);
    __syncthreads();
    if (lane == 0) sh[wid] = v;
    __syncthreads();
    if (wid == 0) {
        float x = (lane < nw) ? sh[lane] : -INFINITY;
        x = warpReduceMax(x);
        if (lane == 0) sh[32] = x;
    }
    __syncthreads();
    return sh[32];
}

// ---------------------------------------------------------------------------
// Warp-per-row LayerNorm + ReLU, split bf16 hi/lo out. 8 rows/block.
// ---------------------------------------------------------------------------
template<int NDIM>
__global__ __launch_bounds__(256)
void ln_relu_split_warp(const float* __restrict__ x, const float* __restrict__ g,
                        const float* __restrict__ b,
                        __nv_bfloat16* __restrict__ hi, __nv_bfloat16* __restrict__ lo)
{
    const int PER = NDIM / 32;
    int w = threadIdx.x >> 5, lane = threadIdx.x & 31;
    size_t row = (size_t)blockIdx.x * 8 + w;
    const float* xr = x + row * NDIM;
    float v[PER];
    float s = 0.f;
    #pragma unroll
    for (int i = 0; i < PER; i++) { v[i] = xr[lane + i * 32]; s += v[i]; }
    s = warpReduceSum(s);
    float mu = s * (1.f / NDIM);
    float s2 = 0.f;
    #pragma unroll
    for (int i = 0; i < PER; i++) { float d = v[i] - mu; s2 += d * d; }
    s2 = warpReduceSum(s2);
    float inv = rsqrtf(s2 * (1.f / NDIM) + LN_EPS);
    size_t ob = row * NDIM;
    #pragma unroll
    for (int i = 0; i < PER; i++) {
        int j = lane + i * 32;
        float y = fmaxf((v[i] - mu) * inv * g[j] + b[j], 0.f);
        __nv_bfloat16 hv = __float2bfloat16(y);
        hi[ob + j] = hv;
        lo[ob + j] = __float2bfloat16(y - __bfloat162float(hv));
    }
}

// Warp-per-row LayerNorm + ReLU in-place fp32 (bottleneck). 8 rows/block.
template<int NDIM>
__global__ __launch_bounds__(256)
void ln_relu_warp(float* __restrict__ x, const float* __restrict__ g,
                  const float* __restrict__ b)
{
    const int PER = NDIM / 32;
    int w = threadIdx.x >> 5, lane = threadIdx.x & 31;
    size_t row = (size_t)blockIdx.x * 8 + w;
    float* xr = x + row * NDIM;
    float v[PER];
    float s = 0.f;
    #pragma unroll
    for (int i = 0; i < PER; i++) { v[i] = xr[lane + i * 32]; s += v[i]; }
    s = warpReduceSum(s);
    float mu = s * (1.f / NDIM);
    float s2 = 0.f;
    #pragma unroll
    for (int i = 0; i < PER; i++) { float d = v[i] - mu; s2 += d * d; }
    s2 = warpReduceSum(s2);
    float inv = rsqrtf(s2 * (1.f / NDIM) + LN_EPS);
    #pragma unroll
    for (int i = 0; i < PER; i++) {
        int j = lane + i * 32;
        xr[j] = fmaxf((v[i] - mu) * inv * g[j] + b[j], 0.f);
    }
}

// ---------------------------------------------------------------------------
// Row softmax (fp16 in) * exp(-5*dist), masked keys zeroed; bf16 out.
// ---------------------------------------------------------------------------
__global__ __launch_bounds__(256)
void softmax_adj_bf16_kernel(const __half* __restrict__ scores,
                             const float* __restrict__ coords,
                             const int* __restrict__ mask,
                             __nv_bfloat16* __restrict__ at_h)
{
    int s = blockIdx.x, b = blockIdx.y;
    size_t rowOff = ((size_t)b * S + s) * S;
    const __half* row = scores + rowOff;
    const float* crow = coords + (size_t)b * S * 3;
    const int* mrow = mask + (size_t)b * S;
    float px = crow[s * 3 + 0], py = crow[s * 3 + 1];
    int tid = threadIdx.x;

    float loc[8];
    float m = -INFINITY;
    #pragma unroll
    for (int i = 0; i < 8; i++) { loc[i] = __half2float(row[tid + i * 256]); m = fmaxf(m, loc[i]); }
    m = blockReduceMax(m);
    float sum = 0.f;
    #pragma unroll
    for (int i = 0; i < 8; i++) { loc[i] = __expf(loc[i] - m); sum += loc[i]; }
    sum = blockReduceSum(sum);
    float inv = 1.f / sum;
    #pragma unroll
    for (int i = 0; i < 8; i++) {
        int t = tid + i * 256;
        float w;
        if (mrow[t] != 0) {
            w = 0.f;
        } else {
            float dx = px - crow[t * 3 + 0];
            float dy = py - crow[t * 3 + 1];
            float sq = dx * dx + dy * dy;
            w = (sq > 0.f) ? __expf(-5.f * sqrtf(sq)) : 1.f;
        }
        at_h[rowOff + t] = __float2bfloat16(loc[i] * inv * w);
    }
}

// ---------------------------------------------------------------------------
// Parallel masked mean pool
// ---------------------------------------------------------------------------
__global__ __launch_bounds__(256)
void pool_partial_kernel(const float* __restrict__ feat, const int* __restrict__ mask,
                         float* __restrict__ partial)
{
    int b = blockIdx.x, sl = blockIdx.y, tid = threadIdx.x;
    __shared__ float sval[256];
    int s0 = sl * 256;
    sval[tid] = (mask[(size_t)b * S + s0 + tid] != 0) ? 0.f : 1.f;
    __syncthreads();
    const float* base = feat + ((size_t)b * S + s0) * BN + tid;
    float a0 = 0.f, a1 = 0.f, a2 = 0.f, a3 = 0.f;
    #pragma unroll 2
    for (int s = 0; s < 256; s += 4) {
        a0 = fmaf(base[(size_t)(s + 0) * BN], sval[s + 0], a0);
        a1 = fmaf(base[(size_t)(s + 1) * BN], sval[s + 1], a1);
        a2 = fmaf(base[(size_t)(s + 2) * BN], sval[s + 2], a2);
        a3 = fmaf(base[(size_t)(s + 3) * BN], sval[s + 3], a3);
    }
    partial[((size_t)b * 8 + sl) * BN + tid] = (a0 + a1) + (a2 + a3);
}

__global__ __launch_bounds__(256)
void pool_reduce_kernel(const float* __restrict__ partial, const int* __restrict__ mask,
                        float* __restrict__ pooled)
{
    int b = blockIdx.x, tid = threadIdx.x;
    float c = 0.f;
    for (int s = tid; s < S; s += 256)
        c += (mask[(size_t)b * S + s] != 0) ? 0.f : 1.f;
    c = blockReduceSum(c);
    float denom = 1.f / fmaxf(c, 1e-9f);
    float a = 0.f;
    #pragma unroll
    for (int sl = 0; sl < 8; sl++)
        a += partial[((size_t)b * 8 + sl) * BN + tid];
    pooled[b * BN + tid] = a * denom;
}

// ---------------------------------------------------------------------------
// Head MLP
// ---------------------------------------------------------------------------
__global__ __launch_bounds__(128)
void head_kernel(const float* __restrict__ pooled,
                 const float* __restrict__ w_c1, const float* __restrict__ b_c1,
                 const float* __restrict__ w_c2, const float* __restrict__ b_c2,
                 float* __restrict__ logits)
{
    int b = blockIdx.x, tid = threadIdx.x;
    __shared__ float p[BN];
    __shared__ float hid[BN / 2];
    for (int i = tid; i < BN; i += 128) p[i] = pooled[b * BN + i];
    __syncthreads();
    float a = b_c1[tid];
    #pragma unroll 8
    for (int i = 0; i < BN; i++) a = fmaf(p[i], w_c1[i * (BN / 2) + tid], a);
    hid[tid] = fmaxf(a, 0.f);
    __syncthreads();
    if (tid < NC) {
        float o = b_c2[tid];
        #pragma unroll 8
        for (int j = 0; j < BN / 2; j++) o = fmaf(hid[j], w_c2[j * NC + tid], o);
        logits[b * NC + tid] = o;
    }
}

// ---------------------------------------------------------------------------
// Launch
// ---------------------------------------------------------------------------
static inline int grid4(size_t n) { return (int)((n / 4 + 255) / 256); }

extern "C" void kernel_launch(void* const* d_in, const int* in_sizes, int n_in,
                              void* d_out, int out_size)
{
    const float* local_feat = (const float*)d_in[0];
    const float* coords     = (const float*)d_in[1];
    const int*   mask       = (const int*)d_in[2];
    const float* w_enc = (const float*)d_in[3];
    const float* b_enc = (const float*)d_in[4];
    const float* ln1_g = (const float*)d_in[5];
    const float* ln1_b = (const float*)d_in[6];
    const float* wq = (const float*)d_in[7];
    const float* bq = (const float*)d_in[8];
    const float* wk = (const float*)d_in[9];
    const float* bk = (const float*)d_in[10];
    const float* wv = (const float*)d_in[11];
    const float* bv = (const float*)d_in[12];
    const float* w_bn = (const float*)d_in[13];
    const float* b_bn = (const float*)d_in[14];
    const float* ln2_g = (const float*)d_in[15];
    const float* ln2_b = (const float*)d_in[16];
    const float* w_c1 = (const float*)d_in[17];
    const float* b_c1 = (const float*)d_in[18];
    const float* w_c2 = (const float*)d_in[19];
    const float* b_c2 = (const float*)d_in[20];
    float* out = (float*)d_out;
    float* logits = out;
    float* pooled = out + B * NC;

    float *tmp, *bnb, *pp;
    __half* sch;
    cudaGetSymbolAddress((void**)&tmp, g_tmp);
    cudaGetSymbolAddress((void**)&sch, g_scores_h);
    cudaGetSymbolAddress((void**)&bnb, g_bn);
    cudaGetSymbolAddress((void**)&pp, g_pp);

    __nv_bfloat16 *lf_h,*lf_l,*h_h,*h_l,*q_h,*q_l,*k_h,*k_l,*v_h,*v_l,*vt_h,*vt_l,*at_h,*hg_h,*hg_l;
    __nv_bfloat16 *we_h,*we_l,*wq_h,*wq_l,*wk_h,*wk_l,*wv_h,*wv_l,*wb_h,*wb_l;
    cudaGetSymbolAddress((void**)&lf_h, g_lf_h); cudaGetSymbolAddress((void**)&lf_l, g_lf_l);
    cudaGetSymbolAddress((void**)&h_h, g_h_h);   cudaGetSymbolAddress((void**)&h_l, g_h_l);
    cudaGetSymbolAddress((void**)&q_h, g_q_h);   cudaGetSymbolAddress((void**)&q_l, g_q_l);
    cudaGetSymbolAddress((void**)&k_h, g_k_h);   cudaGetSymbolAddress((void**)&k_l, g_k_l);
    cudaGetSymbolAddress((void**)&v_h, g_v_h);   cudaGetSymbolAddress((void**)&v_l, g_v_l);
    cudaGetSymbolAddress((void**)&vt_h, g_vt_h); cudaGetSymbolAddress((void**)&vt_l, g_vt_l);
    cudaGetSymbolAddress((void**)&at_h, g_at_h);
    cudaGetSymbolAddress((void**)&hg_h, g_hg_h); cudaGetSymbolAddress((void**)&hg_l, g_hg_l);
    cudaGetSymbolAddress((void**)&we_h, g_we_h); cudaGetSymbolAddress((void**)&we_l, g_we_l);
    cudaGetSymbolAddress((void**)&wq_h, g_wq_h); cudaGetSymbolAddress((void**)&wq_l, g_wq_l);
    cudaGetSymbolAddress((void**)&wk_h, g_wk_h); cudaGetSymbolAddress((void**)&wk_l, g_wk_l);
    cudaGetSymbolAddress((void**)&wv_h, g_wv_h); cudaGetSymbolAddress((void**)&wv_l, g_wv_l);
    cudaGetSymbolAddress((void**)&wb_h, g_wb_h); cudaGetSymbolAddress((void**)&wb_l, g_wb_l);

    cudaFuncSetAttribute(gemm_tc_kernel<true, 0, 2>,  cudaFuncAttributeMaxDynamicSharedMemorySize, GEMM_SMEM_BYTES);
    cudaFuncSetAttribute(gemm_tc_kernel<false, 2, 2>, cudaFuncAttributeMaxDynamicSharedMemorySize, GEMM_SMEM_BYTES);
    cudaFuncSetAttribute(gemm_tc_kernel<false, 1, 1>, cudaFuncAttributeMaxDynamicSharedMemorySize, GEMM_SMEM_BYTES);
    cudaFuncSetAttribute(qkv_kernel, cudaFuncAttributeMaxDynamicSharedMemorySize, GEMM_SMEM_BYTES);

    dim3 tb(32, 8);

    // Launch 0: no-op (aligns ncu sampling onto the encoder GEMM at index 3)
    noop_kernel<<<1, 32>>>();

    // Launch 1-2: split local_feat + weight transposes
    split_kernel<<<grid4((size_t)M_TOT * CLIP), 256>>>(local_feat, lf_h, lf_l, (size_t)M_TOT * CLIP / 4);
    {
        WTArgs wa;
        wa.in[0] = w_enc; wa.hi[0] = we_h; wa.lo[0] = we_l; wa.R[0] = CLIP; wa.C[0] = H;
        wa.in[1] = wq;    wa.hi[1] = wq_h; wa.lo[1] = wq_l; wa.R[1] = H;    wa.C[1] = H;
        wa.in[2] = wk;    wa.hi[2] = wk_h; wa.lo[2] = wk_l; wa.R[2] = H;    wa.C[2] = H;
        wa.in[3] = wv;    wa.hi[3] = wv_h; wa.lo[3] = wv_l; wa.R[3] = H;    wa.C[3] = H;
        wa.in[4] = w_bn;  wa.hi[4] = wb_h; wa.lo[4] = wb_l; wa.R[4] = H;    wa.C[4] = BN;
        weights_transpose_kernel<<<dim3(16, 16, 5), tb>>>(wa);
    }

    // Launch 3: encoder GEMM ; Launch 4: LN1 (warp) -> split h
    gemm_tc_kernel<true, 0, 2><<<dim3(H / TILE_N, M_TOT / TILE_M2, 1), 256, GEMM_SMEM_BYTES>>>(
        lf_h, lf_l, we_h, we_l, b_enc, tmp, nullptr, nullptr, CLIP, H, 1.f, 0, 0, 0);
    ln_relu_split_warp<H><<<M_TOT / 8, 256>>>(tmp, ln1_g, ln1_b, h_h, h_l);

    // merged Q/K/V projections (bf16 hi/lo out), M=256 body
    {
        QKVArgs qa;
        qa.bh[0] = wq_h; qa.bl[0] = wq_l; qa.bias[0] = bq; qa.ch[0] = q_h; qa.cl[0] = q_l;
        qa.bh[1] = wk_h; qa.bl[1] = wk_l; qa.bias[1] = bk; qa.ch[1] = k_h; qa.cl[1] = k_l;
        qa.bh[2] = wv_h; qa.bl[2] = wv_l; qa.bias[2] = bv; qa.ch[2] = v_h; qa.cl[2] = v_l;
        qkv_kernel<<<dim3(H / TILE_N, M_TOT / TILE_M2, 3), 256, GEMM_SMEM_BYTES>>>(h_h, h_l, qa);
    }

    // transpose v (hi and lo, bf16)
    transpose_bf16_kernel<<<dim3(H / 32, S / 32, 2 * B), tb>>>(
        v_h, v_l, vt_h, vt_l, S, H, (size_t)S * H, (size_t)H * S);

    // scores = q @ k^T / sqrt(H) -> fp16
    gemm_tc_kernel<false, 2, 2><<<dim3(S / TILE_N, S / TILE_M2, B), 256, GEMM_SMEM_BYTES>>>(
        q_h, q_l, k_h, k_l, nullptr, nullptr, (__nv_bfloat16*)sch, nullptr, H, S,
        1.f / sqrtf((float)H),
        (size_t)S * H, (size_t)S * H, (size_t)S * S);

    // softmax + adjacency + mask -> bf16 attn
    softmax_adj_bf16_kernel<<<dim3(S, B), 256>>>(sch, coords, mask, at_h);

    // h_graph = attn @ v (A single-term), bf16 hi/lo out
    gemm_tc_kernel<false, 1, 1><<<dim3(H / TILE_N, S / TILE_M2, B), 256, GEMM_SMEM_BYTES>>>(
        at_h, at_h, vt_h, vt_l, nullptr, nullptr, hg_h, hg_l, S, H, 1.f,
        (size_t)S * S, (size_t)H * S, (size_t)S * H);

    // bottleneck GEMM + bias -> fp32 ; LN2 (warp) in place
    gemm_tc_kernel<true, 0, 2><<<dim3(BN / TILE_N, M_TOT / TILE_M2, 1), 256, GEMM_SMEM_BYTES>>>(
        hg_h, hg_l, wb_h, wb_l, b_bn, bnb, nullptr, nullptr, H, BN, 1.f, 0, 0, 0);
    ln_relu_warp<BN><<<M_TOT / 8, 256>>>(bnb, ln2_g, ln2_b);

    // pool (parallel) + head
    pool_partial_kernel<<<dim3(B, 8), 256>>>(bnb, mask, pp);
    pool_reduce_kernel<<<B, 256>>>(pp, mask, pooled);
    head_kernel<<<B, 128>>>(pooled, w_c1, b_c1, w_c2, b_c2, logits);
}

// round 14
// speedup vs baseline: 1.6445x; 1.6445x over previous
#include <cuda_runtime.h>
#include <cuda_bf16.h>
#include <cuda_fp16.h>
#include <math.h>
#include <stdint.h>

// Problem constants
#define B    8
#define S    2048
#define CLIP 512
#define H    512
#define BN   256
#define NC   10
#define LN_EPS 1e-5f
#define M_TOT (B * S)   // 16384

#if defined(__CUDA_ARCH_FEAT_SM103_ALL) || defined(__CUDA_ARCH_FEAT_SM100_ALL) || defined(__CUDA_ARCH_FEAT_SM101_ALL)
#define HAS_TCGEN05 1
#else
#define HAS_TCGEN05 0
#endif

// ---------------------------------------------------------------------------
// Scratch (fp16 single-term operands)
// ---------------------------------------------------------------------------
__device__ float g_tmp[M_TOT * H];              // enc pre-LN
__device__ float g_bn[M_TOT * BN];              // bottleneck pre-LN
__device__ float g_pp[B * 8 * BN];              // pool partials

__device__ __align__(256) __half g_lf[M_TOT * CLIP];
__device__ __align__(256) __half g_h[M_TOT * H];
__device__ __align__(256) __half g_q[M_TOT * H];
__device__ __align__(256) __half g_k[M_TOT * H];
__device__ __align__(256) __half g_v[M_TOT * H];
__device__ __align__(256) __half g_vt[B * H * S];
__device__ __align__(256) __half g_sc[(size_t)B * S * S];   // fp16 scores
__device__ __align__(256) __half g_at[(size_t)B * S * S];   // fp16 attn
__device__ __align__(256) __half g_hg[M_TOT * H];
__device__ __align__(256) __half g_we[H * CLIP];
__device__ __align__(256) __half g_wq[H * H];
__device__ __align__(256) __half g_wk[H * H];
__device__ __align__(256) __half g_wv[H * H];
__device__ __align__(256) __half g_wb[BN * H];

#define TILE_M2 256     // M per CTA (2 TMEM accumulators of 128 rows)
#define TILE_N 256
#define KC 64           // K per chunk (SW128, 128B rows of fp16)
#define NSTG 3
#define STAGE_SZ 65536u // A 32KB + B 32KB
#define GEMM_SMEM_BYTES (NSTG * 65536 + 1024)

#if HAS_TCGEN05
// ---------------------------------------------------------------------------
// PTX helpers (tcgen05 / mbarrier / cp.async, sm_103a)
// ---------------------------------------------------------------------------
__device__ __forceinline__ uint32_t smem_u32(const void* p) {
    return (uint32_t)__cvta_generic_to_shared(p);
}
__device__ __forceinline__ bool elect_one() {
    uint32_t pred;
    asm volatile("{\n\t.reg .pred p;\n\telect.sync _|p, 0xFFFFFFFF;\n\tselp.b32 %0, 1, 0, p;\n\t}"
                 : "=r"(pred));
    return pred != 0;
}
__device__ __forceinline__ void mbar_init(uint32_t a, uint32_t cnt) {
    asm volatile("mbarrier.init.shared.b64 [%0], %1;" :: "r"(a), "r"(cnt) : "memory");
}
__device__ __forceinline__ void mbar_inval(uint32_t a) {
    asm volatile("mbarrier.inval.shared.b64 [%0];" :: "r"(a) : "memory");
}
__device__ __forceinline__ void mbar_wait(uint32_t a, uint32_t parity) {
    asm volatile(
        "{\n\t.reg .pred P;\n"
        "W_%=:\n\t"
        "mbarrier.try_wait.parity.acquire.cta.shared::cta.b64 P, [%0], %1, 0x989680;\n\t"
        "@P bra.uni D_%=;\n\t"
        "bra.uni W_%=;\n"
        "D_%=:\n\t}"
        :: "r"(a), "r"(parity) : "memory");
}
__device__ __forceinline__ void tc_alloc(uint32_t smem_ptr_addr, uint32_t ncols) {
    asm volatile("tcgen05.alloc.cta_group::1.sync.aligned.shared::cta.b32 [%0], %1;"
                 :: "r"(smem_ptr_addr), "r"(ncols) : "memory");
}
__device__ __forceinline__ void tc_dealloc(uint32_t tmem, uint32_t ncols) {
    asm volatile("tcgen05.dealloc.cta_group::1.sync.aligned.b32 %0, %1;" :: "r"(tmem), "r"(ncols));
}
__device__ __forceinline__ void tc_relinquish() {
    asm volatile("tcgen05.relinquish_alloc_permit.cta_group::1.sync.aligned;");
}
__device__ __forceinline__ void tc_commit(uint32_t mbar) {
    asm volatile("tcgen05.commit.cta_group::1.mbarrier::arrive::one.shared::cluster.b64 [%0];"
                 :: "r"(mbar) : "memory");
}
__device__ __forceinline__ void tc_fence_after() {
    asm volatile("tcgen05.fence::after_thread_sync;" ::: "memory");
}
__device__ __forceinline__ void tc_wait_ld() {
    asm volatile("tcgen05.wait::ld.sync.aligned;" ::: "memory");
}
__device__ __forceinline__ void mma_ss(uint32_t d, uint64_t a, uint64_t b, uint32_t idesc, uint32_t en) {
    asm volatile(
        "{\n\t"
        ".reg .pred p;\n\t"
        "setp.ne.u32 p, %5, 0;\n\t"
        "tcgen05.mma.cta_group::1.kind::f16 [%0], %1, %2, %3, {%4, %4, %4, %4}, p;\n\t"
        "}"
        :: "r"(d), "l"(a), "l"(b), "r"(idesc), "r"(0u), "r"(en) : "memory");
}
__device__ __forceinline__ void ldtm_x32(uint32_t* r, uint32_t addr) {
    asm volatile(
        "tcgen05.ld.sync.aligned.32x32b.x32.b32 "
        "{%0, %1, %2, %3, %4, %5, %6, %7, "
        " %8, %9, %10, %11, %12, %13, %14, %15, "
        " %16, %17, %18, %19, %20, %21, %22, %23, "
        " %24, %25, %26, %27, %28, %29, %30, %31}, [%32];"
        : "=r"(r[0]),  "=r"(r[1]),  "=r"(r[2]),  "=r"(r[3]),
          "=r"(r[4]),  "=r"(r[5]),  "=r"(r[6]),  "=r"(r[7]),
          "=r"(r[8]),  "=r"(r[9]),  "=r"(r[10]), "=r"(r[11]),
          "=r"(r[12]), "=r"(r[13]), "=r"(r[14]), "=r"(r[15]),
          "=r"(r[16]), "=r"(r[17]), "=r"(r[18]), "=r"(r[19]),
          "=r"(r[20]), "=r"(r[21]), "=r"(r[22]), "=r"(r[23]),
          "=r"(r[24]), "=r"(r[25]), "=r"(r[26]), "=r"(r[27]),
          "=r"(r[28]), "=r"(r[29]), "=r"(r[30]), "=r"(r[31])
        : "r"(addr));
}
// SW128 K-major descriptor (validated R5-R7): layout=2, version=1, SBO=64, LBO=1
__device__ __forceinline__ uint64_t make_desc(uint32_t addr) {
    const uint64_t base = (2ull << 61) | (1ull << 46) | (64ull << 32) | (1ull << 16);
    return base | (uint64_t)((addr >> 4) & 0x3FFF);
}
__device__ __forceinline__ uint32_t swz(uint32_t o) { return o ^ ((o >> 3) & 0x70); }
__device__ __forceinline__ void cp16(uint32_t dst, const void* src) {
    asm volatile("cp.async.cg.shared.global [%0], [%1], 16;" :: "r"(dst), "l"(src) : "memory");
}
__device__ __forceinline__ void cp_commit() { asm volatile("cp.async.commit_group;" ::: "memory"); }
__device__ __forceinline__ void cp_wait0()  { asm volatile("cp.async.wait_group 0;" ::: "memory"); }
__device__ __forceinline__ void cp_wait1()  { asm volatile("cp.async.wait_group 1;" ::: "memory"); }
#endif  // HAS_TCGEN05

// ---------------------------------------------------------------------------
// GEMM body: C = alpha * A @ B^T (+bias), fp16 single-term, tcgen05.
// M=256 per CTA (2 TMEM accumulators); B staged once per chunk.
// KC=64 fp16 (SW128, 128B rows), 3-stage cp.async pipeline.
// Last chunk uses wait_group 0 (race fix, validated R13).
// OMODE 0: fp32 out (C). OMODE 1: fp16 out (H16).
// ---------------------------------------------------------------------------
template<bool BIAS, int OMODE>
__device__ __forceinline__ void gemm_body(
    const __half* __restrict__ A, const __half* __restrict__ Bm,
    const float* __restrict__ bias, float* __restrict__ C, __half* __restrict__ H16,
    int K, int ldC, float alpha, int mBase, int nBase, size_t cOff, char* dynsmem)
{
#if HAS_TCGEN05
    __shared__ uint32_t s_tmemptr[1];
    __shared__ __align__(8) uint64_t s_mbar[NSTG];

    const int tid = threadIdx.x;
    uint32_t sraw = smem_u32(dynsmem);
    uint32_t sA = (sraw + 1023u) & ~1023u;

    uint32_t mb[NSTG];
    #pragma unroll
    for (int i = 0; i < NSTG; i++) mb[i] = smem_u32(&s_mbar[i]);
    const uint32_t tptr = smem_u32(s_tmemptr);

    if (tid == 0) {
        #pragma unroll
        for (int i = 0; i < NSTG; i++) mbar_init(mb[i], 1);
    }
    if (tid < 32) { tc_alloc(tptr, 512); tc_relinquish(); }
    __syncthreads();
    const uint32_t tmem = s_tmemptr[0];

    // kind::f16, fp16 inputs (atype/btype = 0), fp32 accum, M=128 per acc, N=256
    const uint32_t IDESC = (1u << 4) | ((TILE_N / 8) << 17) | ((128 / 16) << 24);

    const int nch = K / KC;
    int phase[NSTG] = {0, 0, 0};

    auto stage = [&](int ch, uint32_t stOff) {
        const int k0 = ch * KC;
        // A: 256 rows x 128B (fp16), SW128
        #pragma unroll
        for (int it = 0; it < 8; it++) {
            int idx = tid + it * 256;          // 0..2047
            int row = idx >> 3, c = idx & 7;   // 8 x 16B per row
            size_t go = (size_t)(mBase + row) * K + k0 + c * 8;
            uint32_t so = swz((uint32_t)(row * 128 + c * 16));
            cp16(sA + stOff + so, A + go);
        }
        // B: 256 rows x 128B at +32KB
        #pragma unroll
        for (int it = 0; it < 8; it++) {
            int idx = tid + it * 256;
            int row = idx >> 3, c = idx & 7;
            size_t go = (size_t)(nBase + row) * K + k0 + c * 8;
            uint32_t so = swz((uint32_t)(row * 128 + c * 16));
            cp16(sA + stOff + 32768 + so, Bm + go);
        }
        cp_commit();
    };

    stage(0, 0);
    stage(1, STAGE_SZ);

    for (int ch = 0; ch < nch; ch++) {
        const int bi = ch % NSTG;
        const uint32_t stOff = (uint32_t)bi * STAGE_SZ;

        if (ch == nch - 1) cp_wait0(); else cp_wait1();
        __syncthreads();

        if (tid < 32) {
            asm volatile("fence.proxy.async.shared::cta;" ::: "memory");
            if (elect_one()) {
                uint64_t dB = make_desc(sA + stOff + 32768);
                #pragma unroll
                for (int acc = 0; acc < 2; acc++) {
                    uint64_t dA = make_desc(sA + stOff + (uint32_t)acc * 16384u);
                    uint32_t dst = tmem + acc * 256;
                    #pragma unroll
                    for (int kk = 0; kk < 4; kk++) {   // KC=64 -> 4 k-steps of 16
                        uint64_t o = (uint64_t)(kk * 2);  // 16 fp16 = 32B = 2 units
                        uint32_t en0 = (ch == 0 && kk == 0) ? 0u : 1u;
                        mma_ss(dst, dA + o, dB + o, IDESC, en0);
                    }
                }
                tc_commit(mb[bi]);
            }
        }

        if (ch + 2 < nch) {
            const int ob = (ch + 2) % NSTG;
            if (ch >= 1) { mbar_wait(mb[ob], (uint32_t)(phase[ob] & 1)); phase[ob]++; }
            stage(ch + 2, (uint32_t)ob * STAGE_SZ);
        }
    }

    #pragma unroll
    for (int b2 = 0; b2 < NSTG; b2++)
        mbar_wait(mb[b2], (uint32_t)(phase[b2] & 1));
    tc_fence_after();

    // Epilogue: 8 warps x 2 accumulators
    {
        int w = tid >> 5, lane = tid & 31;
        int sub = w & 3, half = w >> 2;
        #pragma unroll 1
        for (int acc = 0; acc < 2; acc++) {
            size_t m = (size_t)mBase + acc * 128 + sub * 32 + lane;
            #pragma unroll 1
            for (int c = 0; c < 4; c++) {
                int cg = half * 4 + c;
                uint32_t r[32];
                ldtm_x32(r, tmem + acc * 256 + cg * 32);
                tc_wait_ld();
                int colBase = nBase + cg * 32;
                if (OMODE == 0) {
                    float* dst = C + cOff + m * (size_t)ldC + colBase;
                    #pragma unroll
                    for (int j = 0; j < 32; j += 4) {
                        float4 o;
                        o.x = __uint_as_float(r[j + 0]) * alpha;
                        o.y = __uint_as_float(r[j + 1]) * alpha;
                        o.z = __uint_as_float(r[j + 2]) * alpha;
                        o.w = __uint_as_float(r[j + 3]) * alpha;
                        if (BIAS) {
                            const float* bp = bias + colBase + j;
                            o.x += bp[0]; o.y += bp[1]; o.z += bp[2]; o.w += bp[3];
                        }
                        *(float4*)(dst + j) = o;
                    }
                } else {
                    __half* dst = H16 + cOff + m * (size_t)ldC + colBase;
                    #pragma unroll
                    for (int j = 0; j < 32; j += 8) {
                        __half2 h2[4];
                        #pragma unroll
                        for (int u = 0; u < 4; u++) {
                            float x0 = __uint_as_float(r[j + u * 2 + 0]) * alpha;
                            float x1 = __uint_as_float(r[j + u * 2 + 1]) * alpha;
                            if (BIAS) {
                                x0 += bias[colBase + j + u * 2 + 0];
                                x1 += bias[colBase + j + u * 2 + 1];
                            }
                            h2[u] = __floats2half2_rn(x0, x1);
                        }
                        uint4 o;
                        o.x = *(uint32_t*)&h2[0]; o.y = *(uint32_t*)&h2[1];
                        o.z = *(uint32_t*)&h2[2]; o.w = *(uint32_t*)&h2[3];
                        *(uint4*)(dst + j) = o;
                    }
                }
            }
        }
    }
    __syncthreads();
    if (tid == 0) {
        #pragma unroll
        for (int i = 0; i < NSTG; i++) mbar_inval(mb[i]);
    }
    __syncthreads();
    if (tid < 32) tc_dealloc(tmem, 512);
#else
    // Fallback for non-sm_103a passes (correctness insurance only).
    const int tid = threadIdx.x;
    for (int idx = tid; idx < TILE_M2 * TILE_N; idx += 256) {
        int mi = mBase + idx / TILE_N;
        int ni = nBase + idx % TILE_N;
        float acc = 0.f;
        for (int kk = 0; kk < K; kk++)
            acc = fmaf(__half2float(A[(size_t)mi * K + kk]),
                       __half2float(Bm[(size_t)ni * K + kk]), acc);
        acc *= alpha;
        if (BIAS) acc += bias[ni];
        size_t off = cOff + (size_t)mi * ldC + ni;
        if (OMODE == 0) C[off] = acc;
        else            H16[off] = __float2half(acc);
    }
#endif
}

template<bool BIAS, int OMODE>
__global__ __launch_bounds__(256)
void gemm_tc_kernel(const __half* __restrict__ A, const __half* __restrict__ Bm,
                    const float* __restrict__ bias, float* __restrict__ C,
                    __half* __restrict__ H16,
                    int K, int ldC, float alpha,
                    size_t strA, size_t strB, size_t strC)
{
    extern __shared__ char dynsmem[];
    gemm_body<BIAS, OMODE>(
        A + (size_t)blockIdx.z * strA, Bm + (size_t)blockIdx.z * strB,
        bias, C, H16, K, ldC, alpha,
        blockIdx.y * TILE_M2, blockIdx.x * TILE_N,
        (size_t)blockIdx.z * strC, dynsmem);
}

// Merged Q/K/V projection
struct QKVArgs {
    const __half* w[3];
    const float* bias[3];
    __half* out[3];
};

__global__ __launch_bounds__(256)
void qkv_kernel(const __half* __restrict__ Ain, QKVArgs a)
{
    extern __shared__ char dynsmem[];
    int z = blockIdx.z;
    gemm_body<true, 1>(Ain, a.w[z], a.bias[z], nullptr, a.out[z],
                       H, H, 1.f, blockIdx.y * TILE_M2, blockIdx.x * TILE_N, 0, dynsmem);
}

// No-op: aligns ncu sampling (index 3 = encoder GEMM)
__global__ void noop_kernel() {}

// ---------------------------------------------------------------------------
// fp32 -> fp16 convert (8 elems/thread)
// ---------------------------------------------------------------------------
__global__ void cvt_kernel(const float* __restrict__ in, __half* __restrict__ out, size_t n4)
{
    size_t i = (size_t)blockIdx.x * blockDim.x + threadIdx.x;
    if (i >= n4) return;
    float4 v = ((const float4*)in)[i];
    __half2 a = __floats2half2_rn(v.x, v.y);
    __half2 b = __floats2half2_rn(v.z, v.w);
    uint2 o; o.x = *(uint32_t*)&a; o.y = *(uint32_t*)&b;
    ((uint2*)out)[i] = o;
}

// ---------------------------------------------------------------------------
// fp16 transpose: [S,H] -> [H,S], batched via z
// ---------------------------------------------------------------------------
__global__ void transpose_h_kernel(const __half* __restrict__ in, __half* __restrict__ out,
                                   int R, int C, size_t strIn, size_t strOut)
{
    __shared__ uint16_t t[32][33];
    const uint16_t* inb = (const uint16_t*)in + (size_t)blockIdx.z * strIn;
    uint16_t* outb = (uint16_t*)out + (size_t)blockIdx.z * strOut;
    int r0 = blockIdx.y * 32, c0 = blockIdx.x * 32;
    #pragma unroll
    for (int i = threadIdx.y; i < 32; i += 8)
        t[i][threadIdx.x] = inb[(size_t)(r0 + i) * C + c0 + threadIdx.x];
    __syncthreads();
    #pragma unroll
    for (int i = threadIdx.y; i < 32; i += 8)
        outb[(size_t)(c0 + i) * R + r0 + threadIdx.x] = t[threadIdx.x][i];
}

// ---------------------------------------------------------------------------
// Combined weight transpose + fp16 convert: 5 weights, z = which.
// ---------------------------------------------------------------------------
struct WTArgs {
    const float* in[5];
    __half* out[5];
    int R[5];
    int C[5];
};

__global__ void weights_transpose_kernel(WTArgs a)
{
    __shared__ float t[32][33];
    int z = blockIdx.z;
    int R = a.R[z], C = a.C[z];
    int r0 = blockIdx.y * 32, c0 = blockIdx.x * 32;
    if (r0 >= R || c0 >= C) return;
    const float* inb = a.in[z];
    #pragma unroll
    for (int i = threadIdx.y; i < 32; i += 8)
        t[i][threadIdx.x] = inb[(size_t)(r0 + i) * C + c0 + threadIdx.x];
    __syncthreads();
    #pragma unroll
    for (int i = threadIdx.y; i < 32; i += 8)
        a.out[z][(size_t)(c0 + i) * R + r0 + threadIdx.x] = __float2half(t[threadIdx.x][i]);
}

// ---------------------------------------------------------------------------
// Reductions
// ---------------------------------------------------------------------------
__device__ __forceinline__ float warpReduceSum(float v) {
    #pragma unroll
    for (int o = 16; o > 0; o >>= 1) v += __shfl_xor_sync(0xffffffffu, v, o);
    return v;
}
__device__ __forceinline__ float warpReduceMax(float v) {
    #pragma unroll
    for (int o = 16; o > 0; o >>= 1) v = fmaxf(v, __shfl_xor_sync(0xffffffffu, v, o));
    return v;
}
__device__ float blockReduceSum(float v) {
    __shared__ float sh[33];
    int lane = threadIdx.x & 31, wid = threadIdx.x >> 5;
    int nw = (blockDim.x + 31) >> 5;
    v = warpReduceSum(v);
    __syncthreads();
    if (lane == 0) sh[wid] = v;
    __syncthreads();
    if (wid == 0) {
        float x = (lane < nw) ? sh[lane] : 0.f;
        x = warpReduceSum(x);
        if (lane == 0) sh[32] = x;
    }
    __syncthreads();
    return sh[32];
}
__device__ float blockReduceMax(float v) {
    __shared__ float sh[33];
    int lane = threadIdx.x & 31, wid = threadIdx.x >> 5;
    int nw = (blockDim.x + 31) >> 5;
    v = warpReduceMax(v);
    __syncthreads();
    if (lane == 0) sh[wid] = v;
    __syncthreads();
    if (wid == 0) {
        float x = (lane < nw) ? sh[lane] : -INFINITY;
        x = warpReduceMax(x);
        if (lane == 0) sh[32] = x;
    }
    __syncthreads();
    return sh[32];
}

// ---------------------------------------------------------------------------
// Warp-per-row LayerNorm + ReLU, fp16 out. 8 rows/block.
// ---------------------------------------------------------------------------
template<int NDIM>
__global__ __launch_bounds__(256)
void ln_relu_cvt_warp(const float* __restrict__ x, const float* __restrict__ g,
                      const float* __restrict__ b, __half* __restrict__ out)
{
    const int PER = NDIM / 32;
    int w = threadIdx.x >> 5, lane = threadIdx.x & 31;
    size_t row = (size_t)blockIdx.x * 8 + w;
    const float* xr = x + row * NDIM;
    float v[PER];
    float s = 0.f;
    #pragma unroll
    for (int i = 0; i < PER; i++) { v[i] = xr[lane + i * 32]; s += v[i]; }
    s = warpReduceSum(s);
    float mu = s * (1.f / NDIM);
    float s2 = 0.f;
    #pragma unroll
    for (int i = 0; i < PER; i++) { float d = v[i] - mu; s2 += d * d; }
    s2 = warpReduceSum(s2);
    float inv = rsqrtf(s2 * (1.f / NDIM) + LN_EPS);
    size_t ob = row * NDIM;
    #pragma unroll
    for (int i = 0; i < PER; i++) {
        int j = lane + i * 32;
        float y = fmaxf((v[i] - mu) * inv * g[j] + b[j], 0.f);
        out[ob + j] = __float2half(y);
    }
}

// Warp-per-row LayerNorm + ReLU in-place fp32 (bottleneck). 8 rows/block.
template<int NDIM>
__global__ __launch_bounds__(256)
void ln_relu_warp(float* __restrict__ x, const float* __restrict__ g,
                  const float* __restrict__ b)
{
    const int PER = NDIM / 32;
    int w = threadIdx.x >> 5, lane = threadIdx.x & 31;
    size_t row = (size_t)blockIdx.x * 8 + w;
    float* xr = x + row * NDIM;
    float v[PER];
    float s = 0.f;
    #pragma unroll
    for (int i = 0; i < PER; i++) { v[i] = xr[lane + i * 32]; s += v[i]; }
    s = warpReduceSum(s);
    float mu = s * (1.f / NDIM);
    float s2 = 0.f;
    #pragma unroll
    for (int i = 0; i < PER; i++) { float d = v[i] - mu; s2 += d * d; }
    s2 = warpReduceSum(s2);
    float inv = rsqrtf(s2 * (1.f / NDIM) + LN_EPS);
    #pragma unroll
    for (int i = 0; i < PER; i++) {
        int j = lane + i * 32;
        xr[j] = fmaxf((v[i] - mu) * inv * g[j] + b[j], 0.f);
    }
}

// ---------------------------------------------------------------------------
// Row softmax (fp16 in) * exp(-5*dist), masked keys zeroed; fp16 out.
// ---------------------------------------------------------------------------
__global__ __launch_bounds__(256)
void softmax_adj_kernel(const __half* __restrict__ scores,
                        const float* __restrict__ coords,
                        const int* __restrict__ mask,
                        __half* __restrict__ at)
{
    int s = blockIdx.x, b = blockIdx.y;
    size_t rowOff = ((size_t)b * S + s) * S;
    const __half* row = scores + rowOff;
    const float* crow = coords + (size_t)b * S * 3;
    const int* mrow = mask + (size_t)b * S;
    float px = crow[s * 3 + 0], py = crow[s * 3 + 1];
    int tid = threadIdx.x;

    float loc[8];
    float m = -INFINITY;
    #pragma unroll
    for (int i = 0; i < 8; i++) { loc[i] = __half2float(row[tid + i * 256]); m = fmaxf(m, loc[i]); }
    m = blockReduceMax(m);
    float sum = 0.f;
    #pragma unroll
    for (int i = 0; i < 8; i++) { loc[i] = __expf(loc[i] - m); sum += loc[i]; }
    sum = blockReduceSum(sum);
    float inv = 1.f / sum;
    #pragma unroll
    for (int i = 0; i < 8; i++) {
        int t = tid + i * 256;
        float w;
        if (mrow[t] != 0) {
            w = 0.f;
        } else {
            float dx = px - crow[t * 3 + 0];
            float dy = py - crow[t * 3 + 1];
            float sq = dx * dx + dy * dy;
            w = (sq > 0.f) ? __expf(-5.f * sqrtf(sq)) : 1.f;
        }
        at[rowOff + t] = __float2half(loc[i] * inv * w);
    }
}

// ---------------------------------------------------------------------------
// Parallel masked mean pool
// ---------------------------------------------------------------------------
__global__ __launch_bounds__(256)
void pool_partial_kernel(const float* __restrict__ feat, const int* __restrict__ mask,
                         float* __restrict__ partial)
{
    int b = blockIdx.x, sl = blockIdx.y, tid = threadIdx.x;
    __shared__ float sval[256];
    int s0 = sl * 256;
    sval[tid] = (mask[(size_t)b * S + s0 + tid] != 0) ? 0.f : 1.f;
    __syncthreads();
    const float* base = feat + ((size_t)b * S + s0) * BN + tid;
    float a0 = 0.f, a1 = 0.f, a2 = 0.f, a3 = 0.f;
    #pragma unroll 2
    for (int s = 0; s < 256; s += 4) {
        a0 = fmaf(base[(size_t)(s + 0) * BN], sval[s + 0], a0);
        a1 = fmaf(base[(size_t)(s + 1) * BN], sval[s + 1], a1);
        a2 = fmaf(base[(size_t)(s + 2) * BN], sval[s + 2], a2);
        a3 = fmaf(base[(size_t)(s + 3) * BN], sval[s + 3], a3);
    }
    partial[((size_t)b * 8 + sl) * BN + tid] = (a0 + a1) + (a2 + a3);
}

__global__ __launch_bounds__(256)
void pool_reduce_kernel(const float* __restrict__ partial, const int* __restrict__ mask,
                        float* __restrict__ pooled)
{
    int b = blockIdx.x, tid = threadIdx.x;
    float c = 0.f;
    for (int s = tid; s < S; s += 256)
        c += (mask[(size_t)b * S + s] != 0) ? 0.f : 1.f;
    c = blockReduceSum(c);
    float denom = 1.f / fmaxf(c, 1e-9f);
    float a = 0.f;
    #pragma unroll
    for (int sl = 0; sl < 8; sl++)
        a += partial[((size_t)b * 8 + sl) * BN + tid];
    pooled[b * BN + tid] = a * denom;
}

// ---------------------------------------------------------------------------
// Head MLP
// ---------------------------------------------------------------------------
__global__ __launch_bounds__(128)
void head_kernel(const float* __restrict__ pooled,
                 const float* __restrict__ w_c1, const float* __restrict__ b_c1,
                 const float* __restrict__ w_c2, const float* __restrict__ b_c2,
                 float* __restrict__ logits)
{
    int b = blockIdx.x, tid = threadIdx.x;
    __shared__ float p[BN];
    __shared__ float hid[BN / 2];
    for (int i = tid; i < BN; i += 128) p[i] = pooled[b * BN + i];
    __syncthreads();
    float a = b_c1[tid];
    #pragma unroll 8
    for (int i = 0; i < BN; i++) a = fmaf(p[i], w_c1[i * (BN / 2) + tid], a);
    hid[tid] = fmaxf(a, 0.f);
    __syncthreads();
    if (tid < NC) {
        float o = b_c2[tid];
        #pragma unroll 8
        for (int j = 0; j < BN / 2; j++) o = fmaf(hid[j], w_c2[j * NC + tid], o);
        logits[b * NC + tid] = o;
    }
}

// ---------------------------------------------------------------------------
// Launch
// ---------------------------------------------------------------------------
static inline int grid4(size_t n) { return (int)((n / 4 + 255) / 256); }

extern "C" void kernel_launch(void* const* d_in, const int* in_sizes, int n_in,
                              void* d_out, int out_size)
{
    const float* local_feat = (const float*)d_in[0];
    const float* coords     = (const float*)d_in[1];
    const int*   mask       = (const int*)d_in[2];
    const float* w_enc = (const float*)d_in[3];
    const float* b_enc = (const float*)d_in[4];
    const float* ln1_g = (const float*)d_in[5];
    const float* ln1_b = (const float*)d_in[6];
    const float* wq = (const float*)d_in[7];
    const float* bq = (const float*)d_in[8];
    const float* wk = (const float*)d_in[9];
    const float* bk = (const float*)d_in[10];
    const float* wv = (const float*)d_in[11];
    const float* bv = (const float*)d_in[12];
    const float* w_bn = (const float*)d_in[13];
    const float* b_bn = (const float*)d_in[14];
    const float* ln2_g = (const float*)d_in[15];
    const float* ln2_b = (const float*)d_in[16];
    const float* w_c1 = (const float*)d_in[17];
    const float* b_c1 = (const float*)d_in[18];
    const float* w_c2 = (const float*)d_in[19];
    const float* b_c2 = (const float*)d_in[20];
    float* out = (float*)d_out;
    float* logits = out;
    float* pooled = out + B * NC;

    float *tmp, *bnb, *pp;
    cudaGetSymbolAddress((void**)&tmp, g_tmp);
    cudaGetSymbolAddress((void**)&bnb, g_bn);
    cudaGetSymbolAddress((void**)&pp, g_pp);

    __half *lf, *h, *q, *k, *v, *vt, *sc, *at, *hg, *we, *wqp, *wkp, *wvp, *wb;
    cudaGetSymbolAddress((void**)&lf, g_lf);
    cudaGetSymbolAddress((void**)&h, g_h);
    cudaGetSymbolAddress((void**)&q, g_q);
    cudaGetSymbolAddress((void**)&k, g_k);
    cudaGetSymbolAddress((void**)&v, g_v);
    cudaGetSymbolAddress((void**)&vt, g_vt);
    cudaGetSymbolAddress((void**)&sc, g_sc);
    cudaGetSymbolAddress((void**)&at, g_at);
    cudaGetSymbolAddress((void**)&hg, g_hg);
    cudaGetSymbolAddress((void**)&we, g_we);
    cudaGetSymbolAddress((void**)&wqp, g_wq);
    cudaGetSymbolAddress((void**)&wkp, g_wk);
    cudaGetSymbolAddress((void**)&wvp, g_wv);
    cudaGetSymbolAddress((void**)&wb, g_wb);

    cudaFuncSetAttribute(gemm_tc_kernel<true, 0>,  cudaFuncAttributeMaxDynamicSharedMemorySize, GEMM_SMEM_BYTES);
    cudaFuncSetAttribute(gemm_tc_kernel<false, 1>, cudaFuncAttributeMaxDynamicSharedMemorySize, GEMM_SMEM_BYTES);
    cudaFuncSetAttribute(qkv_kernel, cudaFuncAttributeMaxDynamicSharedMemorySize, GEMM_SMEM_BYTES);

    dim3 tb(32, 8);

    // Launch 0: no-op (keeps ncu sampling on encoder GEMM at index 3)
    noop_kernel<<<1, 32>>>();

    // Launch 1-2: convert local_feat; weight transposes+convert
    cvt_kernel<<<grid4((size_t)M_TOT * CLIP), 256>>>(local_feat, lf, (size_t)M_TOT * CLIP / 4);
    {
        WTArgs wa;
        wa.in[0] = w_enc; wa.out[0] = we;  wa.R[0] = CLIP; wa.C[0] = H;
        wa.in[1] = wq;    wa.out[1] = wqp; wa.R[1] = H;    wa.C[1] = H;
        wa.in[2] = wk;    wa.out[2] = wkp; wa.R[2] = H;    wa.C[2] = H;
        wa.in[3] = wv;    wa.out[3] = wvp; wa.R[3] = H;    wa.C[3] = H;
        wa.in[4] = w_bn;  wa.out[4] = wb;  wa.R[4] = H;    wa.C[4] = BN;
        weights_transpose_kernel<<<dim3(16, 16, 5), tb>>>(wa);
    }

    // Launch 3: encoder GEMM -> fp32 tmp ; Launch 4: LN1 -> fp16 h
    gemm_tc_kernel<true, 0><<<dim3(H / TILE_N, M_TOT / TILE_M2, 1), 256, GEMM_SMEM_BYTES>>>(
        lf, we, b_enc, tmp, nullptr, CLIP, H, 1.f, 0, 0, 0);
    ln_relu_cvt_warp<H><<<M_TOT / 8, 256>>>(tmp, ln1_g, ln1_b, h);

    // merged Q/K/V projections (fp16 out)
    {
        QKVArgs qa;
        qa.w[0] = wqp; qa.bias[0] = bq; qa.out[0] = q;
        qa.w[1] = wkp; qa.bias[1] = bk; qa.out[1] = k;
        qa.w[2] = wvp; qa.bias[2] = bv; qa.out[2] = v;
        qkv_kernel<<<dim3(H / TILE_N, M_TOT / TILE_M2, 3), 256, GEMM_SMEM_BYTES>>>(h, qa);
    }

    // transpose v -> vt [H,S]
    transpose_h_kernel<<<dim3(H / 32, S / 32, B), tb>>>(v, vt, S, H,
                                                        (size_t)S * H, (size_t)H * S);

    // scores = q @ k^T / sqrt(H) -> fp16
    gemm_tc_kernel<false, 1><<<dim3(S / TILE_N, S / TILE_M2, B), 256, GEMM_SMEM_BYTES>>>(
        q, k, nullptr, nullptr, sc, H, S, 1.f / sqrtf((float)H),
        (size_t)S * H, (size_t)S * H, (size_t)S * S);

    // softmax + adjacency + mask -> fp16 attn
    softmax_adj_kernel<<<dim3(S, B), 256>>>(sc, coords, mask, at);

    // h_graph = attn @ v -> fp16
    gemm_tc_kernel<false, 1><<<dim3(H / TILE_N, S / TILE_M2, B), 256, GEMM_SMEM_BYTES>>>(
        at, vt, nullptr, nullptr, hg, S, H, 1.f,
        (size_t)S * S, (size_t)H * S, (size_t)S * H);

    // bottleneck GEMM + bias -> fp32 ; LN2 in place
    gemm_tc_kernel<true, 0><<<dim3(BN / TILE_N, M_TOT / TILE_M2, 1), 256, GEMM_SMEM_BYTES>>>(
        hg, wb, b_bn, bnb, nullptr, H, BN, 1.f, 0, 0, 0);
    ln_relu_warp<BN><<<M_TOT / 8, 256>>>(bnb, ln2_g, ln2_b);

    // pool (parallel) + head
    pool_partial_kernel<<<dim3(B, 8), 256>>>(bnb, mask, pp);
    pool_reduce_kernel<<<B, 256>>>(pp, mask, pooled);
    head_kernel<<<B, 128>>>(pooled, w_c1, b_c1, w_c2, b_c2, logits);
}